// round 9
// baseline (speedup 1.0000x reference)
#include <cuda_runtime.h>
#include <cuda_fp16.h>

#define NMAX 100000
#define EMAX 1600000
#define F1 128
#define F2 64
#define BN_EPS 1e-5f
#define SCAN_B 1024

// ---- scratch (device globals; no allocation allowed) ----
__device__ float  g_dis[NMAX];             // rsqrt(degree)
__device__ int    g_degi[NMAX];            // in-degree (edges only)
__device__ int    g_row[NMAX];             // CSR row start
__device__ int    g_cursor[NMAX];          // fill cursor
__device__ int    g_pub[128];              // scan block totals (+1 flag)
__device__ int    g_csr[EMAX];             // src indices grouped by dst
__device__ uint4  g_H1h[NMAX * 16];        // fp16 dis*(x@W1^T)        [N,128]
__device__ float4 g_AGG1[NMAX * 32];       // layer-1 aggregated fp32  [N,128]
__device__ uint4  g_H2h[NMAX * 8];         // fp16 dis*(relu(bn)@W2^T) [N,64]
__device__ float  g_sums[2 * F1];          // BN sum / sumsq
__device__ uint4  g_W1h4[F1 * F1 / 8];     // fp16 W1 row-major [c][k]; 16 uint4/row
__device__ uint4  g_W2h4[F1 * F2 / 8];     // fp16 W2 row-major [c][k]; 16 uint4/row

// ---- fp16 mma m16n8k16 (row.col, f32 accum) ----
__device__ __forceinline__ void mma_f16(float* d, const unsigned* a, const unsigned* b) {
    asm volatile(
        "mma.sync.aligned.m16n8k16.row.col.f32.f16.f16.f32 "
        "{%0,%1,%2,%3}, {%4,%5,%6,%7}, {%8,%9}, {%0,%1,%2,%3};"
        : "+f"(d[0]), "+f"(d[1]), "+f"(d[2]), "+f"(d[3])
        : "r"(a[0]), "r"(a[1]), "r"(a[2]), "r"(a[3]), "r"(b[0]), "r"(b[1]));
}

__device__ __forceinline__ unsigned pack_half2(float a, float b) {
    __half2 h = __floats2half2_rn(a, b);
    return *reinterpret_cast<unsigned*>(&h);
}

// fp16 row accumulate: acc[0..7] += unpack(u)
__device__ __forceinline__ void acc_u4(float* acc, uint4 u) {
    float2 f0 = __half22float2(*(__half2*)&u.x);
    float2 f1 = __half22float2(*(__half2*)&u.y);
    float2 f2 = __half22float2(*(__half2*)&u.z);
    float2 f3 = __half22float2(*(__half2*)&u.w);
    acc[0] += f0.x; acc[1] += f0.y;
    acc[2] += f1.x; acc[3] += f1.y;
    acc[4] += f2.x; acc[5] += f2.y;
    acc[6] += f3.x; acc[7] += f3.y;
}

// ---------------------------------------------------------------------------
// merged init: zero degrees + BN sums + scan flags, convert weights to fp16
// ---------------------------------------------------------------------------
__global__ void k_init(const float* __restrict__ W1,
                       const float* __restrict__ W2, int n) {
    int i = blockIdx.x * blockDim.x + threadIdx.x;
    if (i < n) g_degi[i] = 0;
    if (i < 2 * F1) g_sums[i] = 0.0f;
    if (i < 128) g_pub[i] = 0;
    if (i < F1 * F1) ((__half*)g_W1h4)[i] = __float2half_rn(W1[i]);
    if (i < F1 * F2) ((__half*)g_W2h4)[i] = __float2half_rn(W2[i]);
}

__global__ void k_deg_count(const int* __restrict__ ei, int e_cnt) {
    int e = blockIdx.x * blockDim.x + threadIdx.x;
    if (e < e_cnt) atomicAdd(&g_degi[ei[e_cnt + e]], 1);
}

// ---------------------------------------------------------------------------
// single-pass scan (publish + lookback); all <=98 blocks co-resident
// ---------------------------------------------------------------------------
__global__ void __launch_bounds__(SCAN_B) k_scan(int n) {
    __shared__ int wtot[32];
    __shared__ int red[32];
    int t = threadIdx.x, b = blockIdx.x;
    int lane = t & 31, wid = t >> 5;
    int i = b * SCAN_B + t;
    int v = (i < n) ? g_degi[i] : 0;

    // warp inclusive scan
    int s = v;
    #pragma unroll
    for (int o = 1; o < 32; o <<= 1) {
        int u = __shfl_up_sync(0xffffffffu, s, o);
        if (lane >= o) s += u;
    }
    if (lane == 31) wtot[wid] = s;
    __syncthreads();
    if (wid == 0) {
        int ws = wtot[lane];
        #pragma unroll
        for (int o = 1; o < 32; o <<= 1) {
            int u = __shfl_up_sync(0xffffffffu, ws, o);
            if (lane >= o) ws += u;
        }
        wtot[lane] = ws;
    }
    __syncthreads();
    int incl = s + (wid ? wtot[wid - 1] : 0);
    int T = wtot[31];

    // publish own total (flag = T+1), then look back at lower blocks
    if (t == 0) atomicExch(&g_pub[b], T + 1);
    int part = 0;
    if (t < b) {
        volatile int* p = &g_pub[t];
        int x;
        while ((x = *p) == 0) {}
        part = x - 1;
    }
    #pragma unroll
    for (int o = 16; o; o >>= 1) part += __shfl_down_sync(0xffffffffu, part, o);
    if (lane == 0) red[wid] = part;
    __syncthreads();
    if (t < 32) {
        int z = red[t];
        #pragma unroll
        for (int o = 16; o; o >>= 1) z += __shfl_down_sync(0xffffffffu, z, o);
        if (t == 0) red[0] = z;
    }
    __syncthreads();
    int off = red[0];

    if (i < n) {
        int start = incl - v + off;       // global exclusive prefix
        g_row[i] = start;
        g_cursor[i] = start;
        g_dis[i] = rsqrtf((float)(v + 1)); // +1 self-loop
    }
}

__global__ void k_csr_fill(const int* __restrict__ ei, int e_cnt) {
    int e = blockIdx.x * blockDim.x + threadIdx.x;
    if (e < e_cnt) {
        int s = ei[e];
        int d = ei[e_cnt + e];
        int pos = atomicAdd(&g_cursor[d], 1);
        g_csr[pos] = s;
    }
}

// ---------------------------------------------------------------------------
// GEMM1 (fp16 mma): H1h = fp16(dis .* (x @ W1^T))
// 256 threads, tile 128x128. Warp w: rows 32*(w>>1), cols 64*(w&1).
// ---------------------------------------------------------------------------
__global__ void __launch_bounds__(256) k_gemm1(const float* __restrict__ x, int n) {
    __shared__ unsigned xs[128][20];
    __shared__ unsigned ws[128][20];
    int t = threadIdx.x;
    int w = t >> 5, lane = t & 31;
    int gid = lane >> 2, tig = lane & 3;
    int rbase = (w >> 1) * 32;
    int cbase = (w & 1) * 64;
    int row0 = blockIdx.x * 128;

    float acc[2][8][4];
    #pragma unroll
    for (int m = 0; m < 2; m++)
        #pragma unroll
        for (int nt = 0; nt < 8; nt++)
            #pragma unroll
            for (int j = 0; j < 4; j++) acc[m][nt][j] = 0.0f;

    for (int kc = 0; kc < F1; kc += 32) {
        for (int i = t; i < 1024; i += 256) {
            int r = i >> 3, kq = i & 7;
            int gr = row0 + r;
            float4 v = make_float4(0.f, 0.f, 0.f, 0.f);
            if (gr < n) v = ((const float4*)x)[gr * 32 + (kc >> 2) + kq];
            xs[r][kq * 2]     = pack_half2(v.x, v.y);
            xs[r][kq * 2 + 1] = pack_half2(v.z, v.w);
        }
        for (int i = t; i < 512; i += 256) {
            int c = i >> 2, q = i & 3;
            *(uint4*)&ws[c][q * 4] = g_W1h4[c * 16 + (kc >> 3) + q];
        }
        __syncthreads();

        #pragma unroll
        for (int ks2 = 0; ks2 < 16; ks2 += 8) {
            unsigned a[2][4], b[8][2];
            #pragma unroll
            for (int m = 0; m < 2; m++) {
                int r0 = rbase + 16 * m + gid;
                a[m][0] = xs[r0][ks2 + tig];
                a[m][1] = xs[r0 + 8][ks2 + tig];
                a[m][2] = xs[r0][ks2 + tig + 4];
                a[m][3] = xs[r0 + 8][ks2 + tig + 4];
            }
            #pragma unroll
            for (int nt = 0; nt < 8; nt++) {
                int c = cbase + 8 * nt + gid;
                b[nt][0] = ws[c][ks2 + tig];
                b[nt][1] = ws[c][ks2 + tig + 4];
            }
            #pragma unroll
            for (int m = 0; m < 2; m++)
                #pragma unroll
                for (int nt = 0; nt < 8; nt++)
                    mma_f16(acc[m][nt], a[m], b[nt]);
        }
        __syncthreads();
    }

    __half2* H1 = (__half2*)g_H1h;
    #pragma unroll
    for (int m = 0; m < 2; m++) {
        int r_lo = row0 + rbase + 16 * m + gid;
        int r_hi = r_lo + 8;
        float dlo = (r_lo < n) ? g_dis[r_lo] : 0.0f;
        float dhi = (r_hi < n) ? g_dis[r_hi] : 0.0f;
        #pragma unroll
        for (int nt = 0; nt < 8; nt++) {
            int c = cbase + 8 * nt + 2 * tig;
            if (r_lo < n)
                H1[r_lo * 64 + (c >> 1)] =
                    __floats2half2_rn(acc[m][nt][0] * dlo, acc[m][nt][1] * dlo);
            if (r_hi < n)
                H1[r_hi * 64 + (c >> 1)] =
                    __floats2half2_rn(acc[m][nt][2] * dhi, acc[m][nt][3] * dhi);
        }
    }
}

// ---------------------------------------------------------------------------
// layer-1 pull aggregation + fused BN stats: half-warp per node
// agg[i] = dis[i]*(H1[i] + sum_{s} H1[s]) + b1
// ---------------------------------------------------------------------------
__global__ void __launch_bounds__(256) k_agg1(const float* __restrict__ b1, int n) {
    __shared__ float ssum[F1];
    __shared__ float ssq[F1];
    int t = threadIdx.x;
    if (t < F1) { ssum[t] = 0.0f; ssq[t] = 0.0f; }
    __syncthreads();

    int i = blockIdx.x * 16 + (t >> 4);
    int q = t & 15;                    // cols 8q..8q+7
    if (i < n) {
        int start = g_row[i];
        int deg   = g_degi[i];
        int endj  = start + deg;
        float acc[8] = {0, 0, 0, 0, 0, 0, 0, 0};
        acc_u4(acc, g_H1h[i * 16 + q]);    // self-loop
        int j = start;
        for (; j + 3 < endj; j += 4) {
            int s0 = __ldg(&g_csr[j]),     s1 = __ldg(&g_csr[j + 1]);
            int s2 = __ldg(&g_csr[j + 2]), s3 = __ldg(&g_csr[j + 3]);
            uint4 u0 = g_H1h[s0 * 16 + q];
            uint4 u1 = g_H1h[s1 * 16 + q];
            uint4 u2 = g_H1h[s2 * 16 + q];
            uint4 u3 = g_H1h[s3 * 16 + q];
            acc_u4(acc, u0); acc_u4(acc, u1); acc_u4(acc, u2); acc_u4(acc, u3);
        }
        for (; j < endj; j++) acc_u4(acc, g_H1h[__ldg(&g_csr[j]) * 16 + q]);

        float di = g_dis[i];
        float4 b0 = ((const float4*)b1)[2 * q];
        float4 b1v = ((const float4*)b1)[2 * q + 1];
        float r0 = fmaf(acc[0], di, b0.x),  r1 = fmaf(acc[1], di, b0.y);
        float r2 = fmaf(acc[2], di, b0.z),  r3 = fmaf(acc[3], di, b0.w);
        float r4 = fmaf(acc[4], di, b1v.x), r5 = fmaf(acc[5], di, b1v.y);
        float r6 = fmaf(acc[6], di, b1v.z), r7 = fmaf(acc[7], di, b1v.w);
        g_AGG1[i * 32 + 2 * q]     = make_float4(r0, r1, r2, r3);
        g_AGG1[i * 32 + 2 * q + 1] = make_float4(r4, r5, r6, r7);
        int c = 8 * q;
        atomicAdd(&ssum[c + 0], r0); atomicAdd(&ssq[c + 0], r0 * r0);
        atomicAdd(&ssum[c + 1], r1); atomicAdd(&ssq[c + 1], r1 * r1);
        atomicAdd(&ssum[c + 2], r2); atomicAdd(&ssq[c + 2], r2 * r2);
        atomicAdd(&ssum[c + 3], r3); atomicAdd(&ssq[c + 3], r3 * r3);
        atomicAdd(&ssum[c + 4], r4); atomicAdd(&ssq[c + 4], r4 * r4);
        atomicAdd(&ssum[c + 5], r5); atomicAdd(&ssq[c + 5], r5 * r5);
        atomicAdd(&ssum[c + 6], r6); atomicAdd(&ssq[c + 6], r6 * r6);
        atomicAdd(&ssum[c + 7], r7); atomicAdd(&ssq[c + 7], r7 * r7);
    }
    __syncthreads();
    if (t < F1) {
        atomicAdd(&g_sums[t], ssum[t]);
        atomicAdd(&g_sums[F1 + t], ssq[t]);
    }
}

// ---------------------------------------------------------------------------
// GEMM2 (fp16 mma): H2h = fp16(dis .* (relu(bn(AGG1)) @ W2^T))
// BN scale/shift computed per-block in prologue (replaces k_bnfinal).
// ---------------------------------------------------------------------------
__global__ void __launch_bounds__(256) k_gemm2(const float* __restrict__ gamma,
                                               const float* __restrict__ beta, int n) {
    __shared__ unsigned xs[128][20];
    __shared__ unsigned ws[64][20];
    __shared__ float sc_s[F1];
    __shared__ float sh_s[F1];
    const float* A = (const float*)g_AGG1;
    int t = threadIdx.x;
    int w = t >> 5, lane = t & 31;
    int gid = lane >> 2, tig = lane & 3;
    int rbase = w * 16;
    int row0 = blockIdx.x * 128;

    if (t < F1) {
        float inv_n = 1.0f / (float)n;
        float mean = g_sums[t] * inv_n;
        float var = g_sums[F1 + t] * inv_n - mean * mean;
        float inv = rsqrtf(var + BN_EPS);
        float sc = gamma[t] * inv;
        sc_s[t] = sc;
        sh_s[t] = beta[t] - mean * sc;
    }
    __syncthreads();

    float acc[8][4];
    #pragma unroll
    for (int nt = 0; nt < 8; nt++)
        #pragma unroll
        for (int j = 0; j < 4; j++) acc[nt][j] = 0.0f;

    for (int kc = 0; kc < F1; kc += 32) {
        for (int i = t; i < 1024; i += 256) {
            int r = i >> 3, kq = i & 7;
            int gr = row0 + r;
            float4 v = make_float4(0.f, 0.f, 0.f, 0.f);
            if (gr < n) {
                int f = kc + kq * 4;
                float4 a = ((const float4*)A)[gr * 32 + (kc >> 2) + kq];
                v.x = fmaxf(fmaf(a.x, sc_s[f + 0], sh_s[f + 0]), 0.0f);
                v.y = fmaxf(fmaf(a.y, sc_s[f + 1], sh_s[f + 1]), 0.0f);
                v.z = fmaxf(fmaf(a.z, sc_s[f + 2], sh_s[f + 2]), 0.0f);
                v.w = fmaxf(fmaf(a.w, sc_s[f + 3], sh_s[f + 3]), 0.0f);
            }
            xs[r][kq * 2]     = pack_half2(v.x, v.y);
            xs[r][kq * 2 + 1] = pack_half2(v.z, v.w);
        }
        if (t < 256) {
            int c = t >> 2, q = t & 3;
            *(uint4*)&ws[c][q * 4] = g_W2h4[c * 16 + (kc >> 3) + q];
        }
        __syncthreads();

        #pragma unroll
        for (int ks2 = 0; ks2 < 16; ks2 += 8) {
            unsigned a[4], b[8][2];
            {
                int r0 = rbase + gid;
                a[0] = xs[r0][ks2 + tig];
                a[1] = xs[r0 + 8][ks2 + tig];
                a[2] = xs[r0][ks2 + tig + 4];
                a[3] = xs[r0 + 8][ks2 + tig + 4];
            }
            #pragma unroll
            for (int nt = 0; nt < 8; nt++) {
                int c = 8 * nt + gid;
                b[nt][0] = ws[c][ks2 + tig];
                b[nt][1] = ws[c][ks2 + tig + 4];
            }
            #pragma unroll
            for (int nt = 0; nt < 8; nt++)
                mma_f16(acc[nt], a, b[nt]);
        }
        __syncthreads();
    }

    __half2* H2 = (__half2*)g_H2h;
    int r_lo = row0 + rbase + gid;
    int r_hi = r_lo + 8;
    float dlo = (r_lo < n) ? g_dis[r_lo] : 0.0f;
    float dhi = (r_hi < n) ? g_dis[r_hi] : 0.0f;
    #pragma unroll
    for (int nt = 0; nt < 8; nt++) {
        int c = 8 * nt + 2 * tig;
        if (r_lo < n)
            H2[r_lo * 32 + (c >> 1)] =
                __floats2half2_rn(acc[nt][0] * dlo, acc[nt][1] * dlo);
        if (r_hi < n)
            H2[r_hi * 32 + (c >> 1)] =
                __floats2half2_rn(acc[nt][2] * dhi, acc[nt][3] * dhi);
    }
}

// ---------------------------------------------------------------------------
// layer-2 pull aggregation: quarter-warp per node, writes d_out directly
// ---------------------------------------------------------------------------
__global__ void __launch_bounds__(256) k_agg2(const float* __restrict__ b2, int n,
                                              float4* __restrict__ out) {
    int t = threadIdx.x;
    int i = blockIdx.x * 32 + (t >> 3);
    int q = t & 7;                     // cols 8q..8q+7
    if (i >= n) return;
    int start = g_row[i];
    int deg   = g_degi[i];
    int endj  = start + deg;
    float acc[8] = {0, 0, 0, 0, 0, 0, 0, 0};
    acc_u4(acc, g_H2h[i * 8 + q]);     // self-loop
    int j = start;
    for (; j + 3 < endj; j += 4) {
        int s0 = __ldg(&g_csr[j]),     s1 = __ldg(&g_csr[j + 1]);
        int s2 = __ldg(&g_csr[j + 2]), s3 = __ldg(&g_csr[j + 3]);
        uint4 u0 = g_H2h[s0 * 8 + q];
        uint4 u1 = g_H2h[s1 * 8 + q];
        uint4 u2 = g_H2h[s2 * 8 + q];
        uint4 u3 = g_H2h[s3 * 8 + q];
        acc_u4(acc, u0); acc_u4(acc, u1); acc_u4(acc, u2); acc_u4(acc, u3);
    }
    for (; j < endj; j++) acc_u4(acc, g_H2h[__ldg(&g_csr[j]) * 8 + q]);

    float di = g_dis[i];
    float4 b0 = ((const float4*)b2)[2 * q];
    float4 b1v = ((const float4*)b2)[2 * q + 1];
    out[i * 16 + 2 * q] =
        make_float4(fmaf(acc[0], di, b0.x), fmaf(acc[1], di, b0.y),
                    fmaf(acc[2], di, b0.z), fmaf(acc[3], di, b0.w));
    out[i * 16 + 2 * q + 1] =
        make_float4(fmaf(acc[4], di, b1v.x), fmaf(acc[5], di, b1v.y),
                    fmaf(acc[6], di, b1v.z), fmaf(acc[7], di, b1v.w));
}

// ---------------------------------------------------------------------------
extern "C" void kernel_launch(void* const* d_in, const int* in_sizes, int n_in,
                              void* d_out, int out_size) {
    const float* x     = (const float*)d_in[0];
    const int*   ei    = (const int*)d_in[1];
    const float* W1    = (const float*)d_in[2];
    const float* b1    = (const float*)d_in[3];
    const float* gamma = (const float*)d_in[4];
    const float* beta  = (const float*)d_in[5];
    const float* W2    = (const float*)d_in[6];
    const float* b2    = (const float*)d_in[7];

    int n = in_sizes[0] / F1;       // 100000
    int e = in_sizes[1] / 2;        // 1600000
    int nb = (n + SCAN_B - 1) / SCAN_B;   // 98 <= 128

    // init + CSR build
    k_init<<<(n + 255) / 256, 256>>>(W1, W2, n);
    k_deg_count<<<(e + 255) / 256, 256>>>(ei, e);
    k_scan<<<nb, SCAN_B>>>(n);
    k_csr_fill<<<(e + 255) / 256, 256>>>(ei, e);

    // layer 1
    k_gemm1<<<(n + 127) / 128, 256>>>(x, n);
    k_agg1<<<(n + 15) / 16, 256>>>(b1, n);

    // layer 2 (BN folded into gemm2 prologue)
    k_gemm2<<<(n + 127) / 128, 256>>>(gamma, beta, n);
    k_agg2<<<(n + 31) / 32, 256>>>(b2, n, (float4*)d_out);
}

// round 10
// speedup vs baseline: 1.3359x; 1.3359x over previous
#include <cuda_runtime.h>
#include <cuda_fp16.h>

#define NMAX 100000
#define EMAX 1600000
#define F1 128
#define F2 64
#define BN_EPS 1e-5f
#define SCAN_B 1024
#define BN_GRID 1024

// ---- scratch (device globals; no allocation allowed) ----
__device__ float  g_dis[NMAX];             // rsqrt(degree)
__device__ int    g_degi[NMAX];            // in-degree (edges only)
__device__ int    g_row[NMAX];             // CSR row start
__device__ int    g_epos[EMAX];            // per-edge rank within destination
__device__ int    g_rowtmp[NMAX];          // block-local exclusive scan
__device__ int    g_bsum[128];             // scan block sums
__device__ int    g_csr[EMAX];             // src indices grouped by dst
__device__ uint4  g_H1h[NMAX * 16];        // fp16 dis*(x@W1^T)        [N,128]
__device__ float4 g_AGG1[NMAX * 32];       // layer-1 aggregated fp32  [N,128]
__device__ uint4  g_H2h[NMAX * 8];         // fp16 dis*(relu(bn)@W2^T) [N,64]
__device__ float  g_sums[2 * F1];          // BN sum / sumsq
__device__ float  g_ss[2 * F1];            // BN scale / shift
__device__ uint4  g_W1h4[F1 * F1 / 8];     // fp16 W1 row-major [c][k]; 16 uint4/row
__device__ uint4  g_W2h4[F1 * F2 / 8];     // fp16 W2 row-major [c][k]; 16 uint4/row

// ---- fp16 mma m16n8k16 (row.col, f32 accum) ----
__device__ __forceinline__ void mma_f16(float* d, const unsigned* a, const unsigned* b) {
    asm volatile(
        "mma.sync.aligned.m16n8k16.row.col.f32.f16.f16.f32 "
        "{%0,%1,%2,%3}, {%4,%5,%6,%7}, {%8,%9}, {%0,%1,%2,%3};"
        : "+f"(d[0]), "+f"(d[1]), "+f"(d[2]), "+f"(d[3])
        : "r"(a[0]), "r"(a[1]), "r"(a[2]), "r"(a[3]), "r"(b[0]), "r"(b[1]));
}

__device__ __forceinline__ unsigned pack_half2(float a, float b) {
    __half2 h = __floats2half2_rn(a, b);
    return *reinterpret_cast<unsigned*>(&h);
}

// fp16 row accumulate: acc[0..7] += unpack(u)
__device__ __forceinline__ void acc_u4(float* acc, uint4 u) {
    float2 f0 = __half22float2(*(__half2*)&u.x);
    float2 f1 = __half22float2(*(__half2*)&u.y);
    float2 f2 = __half22float2(*(__half2*)&u.z);
    float2 f3 = __half22float2(*(__half2*)&u.w);
    acc[0] += f0.x; acc[1] += f0.y;
    acc[2] += f1.x; acc[3] += f1.y;
    acc[4] += f2.x; acc[5] += f2.y;
    acc[6] += f3.x; acc[7] += f3.y;
}

// ---------------------------------------------------------------------------
// merged init: zero degrees + BN sums, convert weights to fp16
// ---------------------------------------------------------------------------
__global__ void k_init(const float* __restrict__ W1,
                       const float* __restrict__ W2, int n) {
    int i = blockIdx.x * blockDim.x + threadIdx.x;
    if (i < n) g_degi[i] = 0;
    if (i < 2 * F1) g_sums[i] = 0.0f;
    if (i < F1 * F1) ((__half*)g_W1h4)[i] = __float2half_rn(W1[i]);
    if (i < F1 * F2) ((__half*)g_W2h4)[i] = __float2half_rn(W2[i]);
}

// count in-degree AND record each edge's rank within its destination
__global__ void k_deg_count(const int* __restrict__ ei, int e_cnt) {
    int e = blockIdx.x * blockDim.x + threadIdx.x;
    if (e < e_cnt) {
        int d = ei[e_cnt + e];
        g_epos[e] = atomicAdd(&g_degi[d], 1);
    }
}

// ---------------------------------------------------------------------------
// scan (2 stages): block-exclusive -> finalize (predecessor-sum in-block)
// ---------------------------------------------------------------------------
__global__ void __launch_bounds__(SCAN_B) k_scan_block(int n) {
    __shared__ int s[SCAN_B];
    int t = threadIdx.x;
    int i = blockIdx.x * SCAN_B + t;
    int v = (i < n) ? g_degi[i] : 0;
    s[t] = v;
    __syncthreads();
    for (int off = 1; off < SCAN_B; off <<= 1) {
        int a = (t >= off) ? s[t - off] : 0;
        __syncthreads();
        s[t] += a;
        __syncthreads();
    }
    if (i < n) g_rowtmp[i] = s[t] - v;
    if (t == SCAN_B - 1) g_bsum[blockIdx.x] = s[t];
}

__global__ void __launch_bounds__(SCAN_B) k_scan_fin(int n, int nb) {
    __shared__ int wsum[32];
    int t = threadIdx.x;
    // sum of predecessor block totals
    int v = (t < nb && t < (int)blockIdx.x) ? g_bsum[t] : 0;
    for (int o = 16; o; o >>= 1) v += __shfl_down_sync(0xffffffffu, v, o);
    if ((t & 31) == 0) wsum[t >> 5] = v;
    __syncthreads();
    if (t < 32) {
        int s2 = wsum[t];
        for (int o = 16; o; o >>= 1) s2 += __shfl_down_sync(0xffffffffu, s2, o);
        if (t == 0) wsum[0] = s2;
    }
    __syncthreads();
    int off = wsum[0];
    int i = blockIdx.x * SCAN_B + t;
    if (i < n) {
        g_row[i] = g_rowtmp[i] + off;
        g_dis[i] = rsqrtf((float)(g_degi[i] + 1));
    }
}

// atomic-free CSR fill using precomputed ranks
__global__ void k_csr_fill(const int* __restrict__ ei, int e_cnt) {
    int e = blockIdx.x * blockDim.x + threadIdx.x;
    if (e < e_cnt) {
        int s = ei[e];
        int d = ei[e_cnt + e];
        g_csr[g_row[d] + g_epos[e]] = s;
    }
}

// ---------------------------------------------------------------------------
// GEMM1 (fp16 mma): H1h = fp16(dis .* (x @ W1^T))
// 256 threads, tile 128x128. Warp w: rows 32*(w>>1), cols 64*(w&1).
// ---------------------------------------------------------------------------
__global__ void __launch_bounds__(256) k_gemm1(const float* __restrict__ x, int n) {
    __shared__ unsigned xs[128][20];
    __shared__ unsigned ws[128][20];
    int t = threadIdx.x;
    int w = t >> 5, lane = t & 31;
    int gid = lane >> 2, tig = lane & 3;
    int rbase = (w >> 1) * 32;
    int cbase = (w & 1) * 64;
    int row0 = blockIdx.x * 128;

    float acc[2][8][4];
    #pragma unroll
    for (int m = 0; m < 2; m++)
        #pragma unroll
        for (int nt = 0; nt < 8; nt++)
            #pragma unroll
            for (int j = 0; j < 4; j++) acc[m][nt][j] = 0.0f;

    for (int kc = 0; kc < F1; kc += 32) {
        for (int i = t; i < 1024; i += 256) {
            int r = i >> 3, kq = i & 7;
            int gr = row0 + r;
            float4 v = make_float4(0.f, 0.f, 0.f, 0.f);
            if (gr < n) v = ((const float4*)x)[gr * 32 + (kc >> 2) + kq];
            xs[r][kq * 2]     = pack_half2(v.x, v.y);
            xs[r][kq * 2 + 1] = pack_half2(v.z, v.w);
        }
        for (int i = t; i < 512; i += 256) {
            int c = i >> 2, q = i & 3;
            *(uint4*)&ws[c][q * 4] = g_W1h4[c * 16 + (kc >> 3) + q];
        }
        __syncthreads();

        #pragma unroll
        for (int ks2 = 0; ks2 < 16; ks2 += 8) {
            unsigned a[2][4], b[8][2];
            #pragma unroll
            for (int m = 0; m < 2; m++) {
                int r0 = rbase + 16 * m + gid;
                a[m][0] = xs[r0][ks2 + tig];
                a[m][1] = xs[r0 + 8][ks2 + tig];
                a[m][2] = xs[r0][ks2 + tig + 4];
                a[m][3] = xs[r0 + 8][ks2 + tig + 4];
            }
            #pragma unroll
            for (int nt = 0; nt < 8; nt++) {
                int c = cbase + 8 * nt + gid;
                b[nt][0] = ws[c][ks2 + tig];
                b[nt][1] = ws[c][ks2 + tig + 4];
            }
            #pragma unroll
            for (int m = 0; m < 2; m++)
                #pragma unroll
                for (int nt = 0; nt < 8; nt++)
                    mma_f16(acc[m][nt], a[m], b[nt]);
        }
        __syncthreads();
    }

    __half2* H1 = (__half2*)g_H1h;
    #pragma unroll
    for (int m = 0; m < 2; m++) {
        int r_lo = row0 + rbase + 16 * m + gid;
        int r_hi = r_lo + 8;
        float dlo = (r_lo < n) ? g_dis[r_lo] : 0.0f;
        float dhi = (r_hi < n) ? g_dis[r_hi] : 0.0f;
        #pragma unroll
        for (int nt = 0; nt < 8; nt++) {
            int c = cbase + 8 * nt + 2 * tig;
            if (r_lo < n)
                H1[r_lo * 64 + (c >> 1)] =
                    __floats2half2_rn(acc[m][nt][0] * dlo, acc[m][nt][1] * dlo);
            if (r_hi < n)
                H1[r_hi * 64 + (c >> 1)] =
                    __floats2half2_rn(acc[m][nt][2] * dhi, acc[m][nt][3] * dhi);
        }
    }
}

// ---------------------------------------------------------------------------
// layer-1 pull aggregation: half-warp (16 lanes) per node, fp16 gather,
// fp32 accumulate. agg[i] = dis[i]*(H1[i] + sum_{s} H1[s]) + b1
// ---------------------------------------------------------------------------
__global__ void __launch_bounds__(256) k_agg1(const float* __restrict__ b1, int n) {
    int t = threadIdx.x;
    int i = blockIdx.x * 16 + (t >> 4);
    int q = t & 15;                    // 16B chunk = 8 halfs = cols 8q..8q+7
    if (i >= n) return;
    int start = g_row[i];
    int deg   = g_degi[i];
    int endj  = start + deg;
    float acc[8] = {0, 0, 0, 0, 0, 0, 0, 0};
    acc_u4(acc, g_H1h[i * 16 + q]);    // self-loop
    int j = start;
    for (; j + 3 < endj; j += 4) {
        int s0 = __ldg(&g_csr[j]),     s1 = __ldg(&g_csr[j + 1]);
        int s2 = __ldg(&g_csr[j + 2]), s3 = __ldg(&g_csr[j + 3]);
        uint4 u0 = g_H1h[s0 * 16 + q];
        uint4 u1 = g_H1h[s1 * 16 + q];
        uint4 u2 = g_H1h[s2 * 16 + q];
        uint4 u3 = g_H1h[s3 * 16 + q];
        acc_u4(acc, u0); acc_u4(acc, u1); acc_u4(acc, u2); acc_u4(acc, u3);
    }
    for (; j < endj; j++) acc_u4(acc, g_H1h[__ldg(&g_csr[j]) * 16 + q]);

    float di = g_dis[i];
    float4 b0 = ((const float4*)b1)[2 * q];
    float4 b1v = ((const float4*)b1)[2 * q + 1];
    g_AGG1[i * 32 + 2 * q] =
        make_float4(fmaf(acc[0], di, b0.x), fmaf(acc[1], di, b0.y),
                    fmaf(acc[2], di, b0.z), fmaf(acc[3], di, b0.w));
    g_AGG1[i * 32 + 2 * q + 1] =
        make_float4(fmaf(acc[4], di, b1v.x), fmaf(acc[5], di, b1v.y),
                    fmaf(acc[6], di, b1v.z), fmaf(acc[7], di, b1v.w));
}

// ---------------------------------------------------------------------------
// BN statistics over AGG1 (L2-resident), 4-deep MLP
// ---------------------------------------------------------------------------
__global__ void k_bnstats(int n) {
    const float* A = (const float*)g_AGG1;
    int c = threadIdx.x;  // 128
    float s = 0.0f, s2 = 0.0f;
    int r = blockIdx.x;
    for (; r + 3 * BN_GRID < n; r += 4 * BN_GRID) {
        float v0 = A[(r) * F1 + c];
        float v1 = A[(r + BN_GRID) * F1 + c];
        float v2 = A[(r + 2 * BN_GRID) * F1 + c];
        float v3 = A[(r + 3 * BN_GRID) * F1 + c];
        s += v0 + v1 + v2 + v3;
        s2 = fmaf(v0, v0, s2); s2 = fmaf(v1, v1, s2);
        s2 = fmaf(v2, v2, s2); s2 = fmaf(v3, v3, s2);
    }
    for (; r < n; r += BN_GRID) {
        float v = A[r * F1 + c];
        s += v;
        s2 = fmaf(v, v, s2);
    }
    atomicAdd(&g_sums[c], s);
    atomicAdd(&g_sums[F1 + c], s2);
}

__global__ void k_bnfinal(const float* __restrict__ gamma,
                          const float* __restrict__ beta, int n) {
    int c = threadIdx.x;
    float inv_n = 1.0f / (float)n;
    float mean = g_sums[c] * inv_n;
    float var = g_sums[F1 + c] * inv_n - mean * mean;
    float inv = rsqrtf(var + BN_EPS);
    float sc = gamma[c] * inv;
    g_ss[c] = sc;
    g_ss[F1 + c] = beta[c] - mean * sc;
}

// ---------------------------------------------------------------------------
// GEMM2 (fp16 mma): H2h = fp16(dis .* (relu(bn(AGG1)) @ W2^T))
// 256 threads, tile 128x64. Warp w: rows 16*w, all 64 cols.
// ---------------------------------------------------------------------------
__global__ void __launch_bounds__(256) k_gemm2(int n) {
    __shared__ unsigned xs[128][20];
    __shared__ unsigned ws[64][20];
    const float* A = (const float*)g_AGG1;
    int t = threadIdx.x;
    int w = t >> 5, lane = t & 31;
    int gid = lane >> 2, tig = lane & 3;
    int rbase = w * 16;
    int row0 = blockIdx.x * 128;

    float acc[8][4];
    #pragma unroll
    for (int nt = 0; nt < 8; nt++)
        #pragma unroll
        for (int j = 0; j < 4; j++) acc[nt][j] = 0.0f;

    for (int kc = 0; kc < F1; kc += 32) {
        for (int i = t; i < 1024; i += 256) {
            int r = i >> 3, kq = i & 7;
            int gr = row0 + r;
            float4 v = make_float4(0.f, 0.f, 0.f, 0.f);
            if (gr < n) {
                int f = kc + kq * 4;
                float4 a = ((const float4*)A)[gr * 32 + (kc >> 2) + kq];
                float4 sc = *(const float4*)&g_ss[f];
                float4 sh = *(const float4*)&g_ss[F1 + f];
                v.x = fmaxf(fmaf(a.x, sc.x, sh.x), 0.0f);
                v.y = fmaxf(fmaf(a.y, sc.y, sh.y), 0.0f);
                v.z = fmaxf(fmaf(a.z, sc.z, sh.z), 0.0f);
                v.w = fmaxf(fmaf(a.w, sc.w, sh.w), 0.0f);
            }
            xs[r][kq * 2]     = pack_half2(v.x, v.y);
            xs[r][kq * 2 + 1] = pack_half2(v.z, v.w);
        }
        if (t < 256) {
            int c = t >> 2, q = t & 3;
            *(uint4*)&ws[c][q * 4] = g_W2h4[c * 16 + (kc >> 3) + q];
        }
        __syncthreads();

        #pragma unroll
        for (int ks2 = 0; ks2 < 16; ks2 += 8) {
            unsigned a[4], b[8][2];
            {
                int r0 = rbase + gid;
                a[0] = xs[r0][ks2 + tig];
                a[1] = xs[r0 + 8][ks2 + tig];
                a[2] = xs[r0][ks2 + tig + 4];
                a[3] = xs[r0 + 8][ks2 + tig + 4];
            }
            #pragma unroll
            for (int nt = 0; nt < 8; nt++) {
                int c = 8 * nt + gid;
                b[nt][0] = ws[c][ks2 + tig];
                b[nt][1] = ws[c][ks2 + tig + 4];
            }
            #pragma unroll
            for (int nt = 0; nt < 8; nt++)
                mma_f16(acc[nt], a, b[nt]);
        }
        __syncthreads();
    }

    __half2* H2 = (__half2*)g_H2h;
    int r_lo = row0 + rbase + gid;
    int r_hi = r_lo + 8;
    float dlo = (r_lo < n) ? g_dis[r_lo] : 0.0f;
    float dhi = (r_hi < n) ? g_dis[r_hi] : 0.0f;
    #pragma unroll
    for (int nt = 0; nt < 8; nt++) {
        int c = 8 * nt + 2 * tig;
        if (r_lo < n)
            H2[r_lo * 32 + (c >> 1)] =
                __floats2half2_rn(acc[nt][0] * dlo, acc[nt][1] * dlo);
        if (r_hi < n)
            H2[r_hi * 32 + (c >> 1)] =
                __floats2half2_rn(acc[nt][2] * dhi, acc[nt][3] * dhi);
    }
}

// ---------------------------------------------------------------------------
// layer-2 pull aggregation: quarter-warp (8 lanes) per node, fp16 gather,
// writes d_out fp32 directly
// ---------------------------------------------------------------------------
__global__ void __launch_bounds__(256) k_agg2(const float* __restrict__ b2, int n,
                                              float4* __restrict__ out) {
    int t = threadIdx.x;
    int i = blockIdx.x * 32 + (t >> 3);
    int q = t & 7;                     // cols 8q..8q+7
    if (i >= n) return;
    int start = g_row[i];
    int deg   = g_degi[i];
    int endj  = start + deg;
    float acc[8] = {0, 0, 0, 0, 0, 0, 0, 0};
    acc_u4(acc, g_H2h[i * 8 + q]);     // self-loop
    int j = start;
    for (; j + 3 < endj; j += 4) {
        int s0 = __ldg(&g_csr[j]),     s1 = __ldg(&g_csr[j + 1]);
        int s2 = __ldg(&g_csr[j + 2]), s3 = __ldg(&g_csr[j + 3]);
        uint4 u0 = g_H2h[s0 * 8 + q];
        uint4 u1 = g_H2h[s1 * 8 + q];
        uint4 u2 = g_H2h[s2 * 8 + q];
        uint4 u3 = g_H2h[s3 * 8 + q];
        acc_u4(acc, u0); acc_u4(acc, u1); acc_u4(acc, u2); acc_u4(acc, u3);
    }
    for (; j < endj; j++) acc_u4(acc, g_H2h[__ldg(&g_csr[j]) * 8 + q]);

    float di = g_dis[i];
    float4 b0 = ((const float4*)b2)[2 * q];
    float4 b1v = ((const float4*)b2)[2 * q + 1];
    out[i * 16 + 2 * q] =
        make_float4(fmaf(acc[0], di, b0.x), fmaf(acc[1], di, b0.y),
                    fmaf(acc[2], di, b0.z), fmaf(acc[3], di, b0.w));
    out[i * 16 + 2 * q + 1] =
        make_float4(fmaf(acc[4], di, b1v.x), fmaf(acc[5], di, b1v.y),
                    fmaf(acc[6], di, b1v.z), fmaf(acc[7], di, b1v.w));
}

// ---------------------------------------------------------------------------
extern "C" void kernel_launch(void* const* d_in, const int* in_sizes, int n_in,
                              void* d_out, int out_size) {
    const float* x     = (const float*)d_in[0];
    const int*   ei    = (const int*)d_in[1];
    const float* W1    = (const float*)d_in[2];
    const float* b1    = (const float*)d_in[3];
    const float* gamma = (const float*)d_in[4];
    const float* beta  = (const float*)d_in[5];
    const float* W2    = (const float*)d_in[6];
    const float* b2    = (const float*)d_in[7];

    int n = in_sizes[0] / F1;       // 100000
    int e = in_sizes[1] / 2;        // 1600000
    int nb = (n + SCAN_B - 1) / SCAN_B;

    // init + CSR build (atomic-free fill via per-edge ranks)
    k_init<<<(n + 255) / 256, 256>>>(W1, W2, n);
    k_deg_count<<<(e + 255) / 256, 256>>>(ei, e);
    k_scan_block<<<nb, SCAN_B>>>(n);
    k_scan_fin<<<nb, SCAN_B>>>(n, nb);
    k_csr_fill<<<(e + 255) / 256, 256>>>(ei, e);

    // layer 1
    k_gemm1<<<(n + 127) / 128, 256>>>(x, n);
    k_agg1<<<(n + 15) / 16, 256>>>(b1, n);

    // BN
    k_bnstats<<<BN_GRID, 128>>>(n);
    k_bnfinal<<<1, 128>>>(gamma, beta, n);

    // layer 2
    k_gemm2<<<(n + 127) / 128, 256>>>(n);
    k_agg2<<<(n + 31) / 32, 256>>>(b2, n, (float4*)d_out);
}